// round 1
// baseline (speedup 1.0000x reference)
#include <cuda_runtime.h>
#include <math_constants.h>

#define ROW_LEN 4096
#define THREADS 512
#define V4_PER_ROW (ROW_LEN / 4)          // 1024
#define V4_PER_THREAD (V4_PER_ROW / THREADS)  // 2
#define NWARPS (THREADS / 32)             // 16

__global__ __launch_bounds__(THREADS)
void masked_softmax_kernel(const float* __restrict__ X,
                           const int* __restrict__ N,
                           float* __restrict__ out) {
    const int row = blockIdx.x;
    const int tid = threadIdx.x;
    const int lane = tid & 31;
    const int wid = tid >> 5;

    const float4* __restrict__ xrow =
        reinterpret_cast<const float4*>(X + (size_t)row * ROW_LEN);
    float4* __restrict__ orow =
        reinterpret_cast<float4*>(out + (size_t)row * ROW_LEN);

    const int n = N[row];  // valid length, in [1, ROW_LEN]

    __shared__ float red[NWARPS];

    // ---- Load entire row into registers (read X exactly once) ----
    float4 v[V4_PER_THREAD];
#pragma unroll
    for (int i = 0; i < V4_PER_THREAD; i++)
        v[i] = xrow[tid + i * THREADS];

    // ---- Masked max ----
    float m = -CUDART_INF_F;
#pragma unroll
    for (int i = 0; i < V4_PER_THREAD; i++) {
        const int base = (tid + i * THREADS) * 4;
        const float* f = reinterpret_cast<const float*>(&v[i]);
#pragma unroll
        for (int j = 0; j < 4; j++)
            if (base + j < n) m = fmaxf(m, f[j]);
    }
#pragma unroll
    for (int o = 16; o > 0; o >>= 1)
        m = fmaxf(m, __shfl_xor_sync(0xFFFFFFFFu, m, o));
    if (lane == 0) red[wid] = m;
    __syncthreads();
    if (wid == 0) {
        float t = (lane < NWARPS) ? red[lane] : -CUDART_INF_F;
#pragma unroll
        for (int o = 16; o > 0; o >>= 1)
            t = fmaxf(t, __shfl_xor_sync(0xFFFFFFFFu, t, o));
        if (lane == 0) red[0] = t;
    }
    __syncthreads();
    m = red[0];
    __syncthreads();  // protect red[] before reuse for the sum

    // ---- exp + masked sum (keep exps in registers) ----
    float e[V4_PER_THREAD * 4];
    float s = 0.0f;
#pragma unroll
    for (int i = 0; i < V4_PER_THREAD; i++) {
        const int base = (tid + i * THREADS) * 4;
        const float* f = reinterpret_cast<const float*>(&v[i]);
#pragma unroll
        for (int j = 0; j < 4; j++) {
            const float ex = __expf(f[j] - m);
            const float ev = (base + j < n) ? ex : 0.0f;
            e[i * 4 + j] = ev;
            s += ev;
        }
    }
#pragma unroll
    for (int o = 16; o > 0; o >>= 1)
        s += __shfl_xor_sync(0xFFFFFFFFu, s, o);
    if (lane == 0) red[wid] = s;
    __syncthreads();
    if (wid == 0) {
        float t = (lane < NWARPS) ? red[lane] : 0.0f;
#pragma unroll
        for (int o = 16; o > 0; o >>= 1)
            t += __shfl_xor_sync(0xFFFFFFFFu, t, o);
        if (lane == 0) red[0] = t;
    }
    __syncthreads();
    const float inv = 1.0f / red[0];

    // ---- Scaled masked write ----
#pragma unroll
    for (int i = 0; i < V4_PER_THREAD; i++) {
        float4 o4;
        o4.x = e[i * 4 + 0] * inv;
        o4.y = e[i * 4 + 1] * inv;
        o4.z = e[i * 4 + 2] * inv;
        o4.w = e[i * 4 + 3] * inv;
        orow[tid + i * THREADS] = o4;
    }
}

extern "C" void kernel_launch(void* const* d_in, const int* in_sizes, int n_in,
                              void* d_out, int out_size) {
    const float* X = (const float*)d_in[0];
    const int* N = (const int*)d_in[1];
    float* out = (float*)d_out;

    const int B = in_sizes[1];  // N has one int per row
    masked_softmax_kernel<<<B, THREADS>>>(X, N, out);
}

// round 3
// speedup vs baseline: 1.0157x; 1.0157x over previous
#include <cuda_runtime.h>
#include <float.h>

#define ROW_LEN 4096
#define THREADS 256
#define V4_PER_THREAD 4                    // 256 * 4 * 4 = 4096 floats
#define NWARPS (THREADS / 32)              // 8

__global__ __launch_bounds__(THREADS)
void masked_softmax_kernel(const float* __restrict__ X,
                           const int* __restrict__ N,
                           float* __restrict__ out) {
    const int row = blockIdx.x;
    const int tid = threadIdx.x;
    const int lane = tid & 31;
    const int wid = tid >> 5;

    const float4* __restrict__ xrow =
        reinterpret_cast<const float4*>(X + (size_t)row * ROW_LEN);
    float4* __restrict__ orow =
        reinterpret_cast<float4*>(out + (size_t)row * ROW_LEN);

    const int n = N[row];  // valid length in [1, ROW_LEN]

    __shared__ float red_m[NWARPS];
    __shared__ float red_s[NWARPS];
    __shared__ float sM, sS;

    // ---- Load entire row into registers (X read exactly once, streaming) ----
    float4 v[V4_PER_THREAD];
#pragma unroll
    for (int i = 0; i < V4_PER_THREAD; i++)
        v[i] = __ldcs(&xrow[tid + i * THREADS]);

    // ---- Per-thread masked max (no barriers) ----
    float m_local = -FLT_MAX;
#pragma unroll
    for (int i = 0; i < V4_PER_THREAD; i++) {
        const int base = (tid + i * THREADS) * 4;
        const float* f = reinterpret_cast<const float*>(&v[i]);
#pragma unroll
        for (int j = 0; j < 4; j++)
            if (base + j < n) m_local = fmaxf(m_local, f[j]);
    }

    // ---- Per-thread exp(x - m_local) + masked local sum ----
    float e[V4_PER_THREAD * 4];
    float s = 0.0f;
#pragma unroll
    for (int i = 0; i < V4_PER_THREAD; i++) {
        const int base = (tid + i * THREADS) * 4;
        const float* f = reinterpret_cast<const float*>(&v[i]);
#pragma unroll
        for (int j = 0; j < 4; j++) {
            const float ex = __expf(f[j] - m_local);
            const float ev = (base + j < n) ? ex : 0.0f;
            e[i * 4 + j] = ev;
            s += ev;
        }
    }

    // ---- Single online (m,s) warp reduction (m_local preserved separately) ----
    float m = m_local;
#pragma unroll
    for (int o = 16; o > 0; o >>= 1) {
        const float mo = __shfl_xor_sync(0xFFFFFFFFu, m, o);
        const float so = __shfl_xor_sync(0xFFFFFFFFu, s, o);
        const float mn = fmaxf(m, mo);
        s = s * __expf(m - mn) + so * __expf(mo - mn);
        m = mn;
    }
    if (lane == 0) { red_m[wid] = m; red_s[wid] = s; }
    __syncthreads();

    // ---- Cross-warp merge in warp 0 ----
    if (wid == 0) {
        float m2 = (lane < NWARPS) ? red_m[lane] : -FLT_MAX;
        float s2 = (lane < NWARPS) ? red_s[lane] : 0.0f;
#pragma unroll
        for (int o = NWARPS / 2; o > 0; o >>= 1) {
            const float mo = __shfl_xor_sync(0xFFFFFFFFu, m2, o);
            const float so = __shfl_xor_sync(0xFFFFFFFFu, s2, o);
            const float mn = fmaxf(m2, mo);
            s2 = s2 * __expf(m2 - mn) + so * __expf(mo - mn);
            m2 = mn;
        }
        if (lane == 0) { sM = m2; sS = s2; }
    }
    __syncthreads();

    // ---- Rescale with the THREAD-LOCAL max:
    //      exp(x - M)/S = e_local * exp(m_local - M) / S ----
    const float scale = __fdividef(__expf(m_local - sM), sS);

#pragma unroll
    for (int i = 0; i < V4_PER_THREAD; i++) {
        float4 o4;
        o4.x = e[i * 4 + 0] * scale;
        o4.y = e[i * 4 + 1] * scale;
        o4.z = e[i * 4 + 2] * scale;
        o4.w = e[i * 4 + 3] * scale;
        __stcs(&orow[tid + i * THREADS], o4);
    }
}

extern "C" void kernel_launch(void* const* d_in, const int* in_sizes, int n_in,
                              void* d_out, int out_size) {
    const float* X = (const float*)d_in[0];
    const int* N = (const int*)d_in[1];
    float* out = (float*)d_out;

    const int B = in_sizes[1];  // one int per row
    masked_softmax_kernel<<<B, THREADS>>>(X, N, out);
}